// round 10
// baseline (speedup 1.0000x reference)
#include <cuda_runtime.h>
#include <cuda_bf16.h>
#include <cstdint>

// GMMVAE ELBO. Stage1: z@W^T via mma.sync bf16, mean staged to smem, x compared
// with coalesced fp32 loads. Stage2 f32x2. Fixed-point single-pass finish.
typedef unsigned long long ull;

#define B_TOT 16384
#define XD 784
#define ZD 64
#define KK 64
#define ROWS 128
#define THREADS 512
#define NBLK (B_TOT / ROWS)   // 128
#define RSTR 66
#define SSTR 116              // staging row stride (floats)
#define LOG2PI 1.8378770664093453
#define FIXSCALE 262144.0

__device__ float g_s2T[ZD * KK];
__device__ float g_na2T[ZD * KK];
__device__ float g_cc2[KK];
__device__ float g_ck2[KK];
__device__ ull g_acc;
__device__ unsigned g_cnt;
__device__ __align__(16) __nv_bfloat16 g_Wt[XD * 64];  // [c][z] 128B swizzled rows

// ---- smem byte offsets ----
#define OFF_RED   0        // 128
#define OFF_BIAS  128      // 3136 -> 3264
#define OFF_WT    3328     // 100352 -> 103680
#define OFF_STG   103680   // 128*116*4 = 59392 -> 163072
#define OFF_ZBF   163072   // 16384 -> 179456
// post-stage1 overlays:
#define OFF_ZR    128      // 33792 -> 33920
#define OFF_V1    33920    // -> 67712
#define OFF_QM    67712    // -> 101504
#define OFF_S2T   101504   // -> 117888
#define OFF_NA2T  117888   // -> 134272
#define OFF_COMP  134272   // -> 167040
#define OFF_KLZ   167040   // -> 199808
#define SMEM_BYTES 199808

__device__ __forceinline__ uint32_t smem_u32(const void* p) {
    uint32_t a;
    asm("{ .reg .u64 t; cvta.to.shared.u64 t, %1; cvt.u32.u64 %0, t; }" : "=r"(a) : "l"(p));
    return a;
}
__device__ __forceinline__ ull fma2o(ull a, ull b, ull c) {
    ull d;
    asm("fma.rn.f32x2 %0, %1, %2, %3;" : "=l"(d) : "l"(a), "l"(b), "l"(c));
    return d;
}
__device__ __forceinline__ ull dup2(float x) {
    ull r;
    asm("mov.b64 %0, {%1, %1};" : "=l"(r) : "f"(x));
    return r;
}
__device__ __forceinline__ void unpack2(ull v, float& lo, float& hi) {
    asm("mov.b64 {%0, %1}, %2;" : "=f"(lo), "=f"(hi) : "l"(v));
}
__device__ __forceinline__ void ldm_x4(uint32_t& r0, uint32_t& r1, uint32_t& r2,
                                       uint32_t& r3, uint32_t addr) {
    asm volatile("ldmatrix.sync.aligned.m8n8.x4.shared.b16 {%0,%1,%2,%3}, [%4];"
                 : "=r"(r0), "=r"(r1), "=r"(r2), "=r"(r3) : "r"(addr));
}
__device__ __forceinline__ void mma_bf16(float& c0, float& c1, float& c2, float& c3,
                                         uint32_t a0, uint32_t a1, uint32_t a2, uint32_t a3,
                                         uint32_t b0, uint32_t b1) {
    asm volatile("mma.sync.aligned.m16n8k16.row.col.f32.bf16.bf16.f32 "
                 "{%0,%1,%2,%3}, {%4,%5,%6,%7}, {%8,%9}, {%0,%1,%2,%3};"
                 : "+f"(c0), "+f"(c1), "+f"(c2), "+f"(c3)
                 : "r"(a0), "r"(a1), "r"(a2), "r"(a3), "r"(b0), "r"(b1));
}
__device__ __forceinline__ uint32_t swz(int r, int zp) {
    return (uint32_t)(r * 128 + (((zp >> 2) ^ (r & 7)) << 4) + 4 * (zp & 3));
}

// ======================= prep kernel (grid 15) =======================
__global__ void prep_kernel(const float* __restrict__ W,
                            const float* __restrict__ pmu,
                            const float* __restrict__ pls) {
    const int b = blockIdx.x, tid = threadIdx.x;
    if (b < 14) {
        __shared__ float sc[64 * 57];
        const int c0 = b * 56;
        for (int i = tid; i < 64 * 56; i += 256) {
            const int z = i / 56, c = i - z * 56;
            sc[z * 57 + c] = W[z * XD + c0 + c];
        }
        __syncthreads();
        for (int i = tid; i < 56 * 32; i += 256) {
            const int c = i >> 5, zp = i & 31;
            __nv_bfloat162 bv = __floats2bfloat162_rn(sc[(2 * zp) * 57 + c],
                                                      sc[(2 * zp + 1) * 57 + c]);
            *(uint32_t*)((char*)g_Wt + swz(c0 + c, zp)) = *(uint32_t*)&bv;
        }
    } else {
        const int k = tid >> 2, q = tid & 3;
        float lsum = 0.f, c1 = 0.f;
#pragma unroll
        for (int i = 0; i < 16; i++) {
            const int z = 16 * q + i;
            float ls = pls[k * ZD + z];
            float mu = pmu[k * ZD + z];
            float s2i = expf(-2.f * ls);
            g_s2T[z * KK + k] = s2i;
            g_na2T[z * KK + k] = -2.f * mu * s2i;
            lsum += ls;
            c1 = fmaf(mu * mu, s2i, c1);
        }
#pragma unroll
        for (int o = 1; o < 4; o <<= 1) {
            lsum += __shfl_xor_sync(~0u, lsum, o);
            c1 += __shfl_xor_sync(~0u, c1, o);
        }
        if (q == 0) {
            g_cc2[k] = (float)(-(double)lsum - 32.0 * LOG2PI - 0.5 * (double)c1);
            g_ck2[k] = lsum + 0.5f * c1;
        }
        if (tid == 0) { g_acc = 0ull; g_cnt = 0u; }
    }
}

// ======================= main kernel =======================
extern __shared__ char smem[];

__global__ __launch_bounds__(THREADS, 1)
void main_kernel(const float* __restrict__ x, const float* __restrict__ pi,
                 const float* __restrict__ qmu, const float* __restrict__ qls,
                 const float* __restrict__ eps, const float* __restrict__ bdec,
                 float* __restrict__ out) {
    const int tid = threadIdx.x;
    const int wid = tid >> 5, lane = tid & 31;
    const int rowbase = blockIdx.x * ROWS;
    const uint32_t sbase = smem_u32(smem);
    float* red = (float*)(smem + OFF_RED);
    float* biasS = (float*)(smem + OFF_BIAS);

    // ---- init: Wt copy, bias, z bf16 (A operand) ----
    {
        const uint4* src = (const uint4*)g_Wt;
        uint4* dst = (uint4*)(smem + OFF_WT);
        for (int i = tid; i < (XD * 128) / 16; i += THREADS) dst[i] = src[i];
    }
    for (int i = tid; i < XD; i += THREADS) biasS[i] = bdec[i];
    for (int i = tid; i < ROWS * 32; i += THREADS) {
        const int r = i >> 5, zp = i & 31;
        const int gi = (rowbase + r) * ZD + 2 * zp;
        float2 qm2 = *(const float2*)(qmu + gi);
        float2 ql2 = *(const float2*)(qls + gi);
        float2 ep2 = *(const float2*)(eps + gi);
        float z0 = fmaf(expf(ql2.x), ep2.x, qm2.x);
        float z1 = fmaf(expf(ql2.y), ep2.y, qm2.y);
        __nv_bfloat162 bv = __floats2bfloat162_rn(z0, z1);
        *(uint32_t*)(smem + OFF_ZBF + swz(r, zp)) = *(uint32_t*)&bv;
    }
    __syncthreads();

    // ================= Stage 1 =================
    float px = 0.f;
    {
        const int g = lane >> 3, lr = lane & 7;
        const int mrow = 16 * (wid & 7);
        const int nh = wid >> 3;

        // A fragments (z rows mrow..mrow+16, K=64)
        uint32_t a[16];
        {
            const int ra = mrow + lr + 8 * (g & 1);
            const uint32_t abase = sbase + OFF_ZBF + ra * 128;
            const int gx = g >> 1;
#pragma unroll
            for (int kt = 0; kt < 4; kt++)
                ldm_x4(a[4 * kt], a[4 * kt + 1], a[4 * kt + 2], a[4 * kt + 3],
                       abase + (uint32_t)(((gx + 2 * kt) ^ (ra & 7)) << 4));
        }
        const uint32_t bbase0 = sbase + OFF_WT + 50176u * nh + lr * 128
                                + (uint32_t)((g ^ lr) << 4);
        const uint32_t bbase1 = sbase + OFF_WT + 50176u * nh + lr * 128
                                + (uint32_t)(((g + 4) ^ lr) << 4);
        // fragment STS mapping
        const int frow0 = mrow + (lane >> 2);
        const int fcol = 2 * (lane & 3);
        // epilogue mapping (28 active lanes)
        const bool eact = lane < 28;
        const int sl = (lane >= 14) ? 1 : 0;
        const int cl = lane - 14 * sl;
        const float* xw = x + (size_t)(rowbase + 8 * wid) * XD + 392 * sl + 4 * cl;
        const uint32_t sRd = sbase + OFF_STG + (uint32_t)((8 * wid) * SSTR + 56 * sl + 4 * cl) * 4;

        for (int r = 0; r < 7; r++) {
            // prefetch x rows 0-3 of this warp's 8
            float4 xfA[4];
            if (eact) {
#pragma unroll
                for (int i = 0; i < 4; i++)
                    xfA[i] = *(const float4*)(xw + (size_t)i * XD + 56 * r);
            }
            // mma: 7 tiles of 8 cols
            float C[7][4];
#pragma unroll
            for (int lt = 0; lt < 7; lt++) {
                uint32_t b[8];
                const uint32_t toff = (uint32_t)(r * 7168 + lt * 1024);
                ldm_x4(b[0], b[1], b[2], b[3], bbase0 + toff);
                ldm_x4(b[4], b[5], b[6], b[7], bbase1 + toff);
                float c0 = 0.f, c1 = 0.f, c2 = 0.f, c3 = 0.f;
                float d0 = 0.f, d1 = 0.f, d2 = 0.f, d3 = 0.f;
                mma_bf16(c0, c1, c2, c3, a[0], a[1], a[2], a[3], b[0], b[1]);
                mma_bf16(d0, d1, d2, d3, a[8], a[9], a[10], a[11], b[4], b[5]);
                mma_bf16(c0, c1, c2, c3, a[4], a[5], a[6], a[7], b[2], b[3]);
                mma_bf16(d0, d1, d2, d3, a[12], a[13], a[14], a[15], b[6], b[7]);
                C[lt][0] = c0 + d0; C[lt][1] = c1 + d1;
                C[lt][2] = c2 + d2; C[lt][3] = c3 + d3;
            }
            __syncthreads();   // prev-round epilogue finished reading staging
            // stage mean+bias
#pragma unroll
            for (int lt = 0; lt < 7; lt++) {
                const int gc = 392 * nh + 56 * r + 8 * lt + fcol;
                float2 bb = *(const float2*)(biasS + gc);
                const int sc = 56 * nh + 8 * lt + fcol;
                *(float2*)(smem + OFF_STG + (size_t)(frow0 * SSTR + sc) * 4) =
                    make_float2(C[lt][0] + bb.x, C[lt][1] + bb.y);
                *(float2*)(smem + OFF_STG + (size_t)((frow0 + 8) * SSTR + sc) * 4) =
                    make_float2(C[lt][2] + bb.x, C[lt][3] + bb.y);
            }
            __syncthreads();   // staging visible
            // epilogue: coalesced x vs staged mean
            if (eact) {
                float4 xfB[4];
#pragma unroll
                for (int i = 0; i < 4; i++)
                    xfB[i] = *(const float4*)(xw + (size_t)(4 + i) * XD + 56 * r);
#pragma unroll
                for (int i = 0; i < 4; i++) {
                    float4 mf = *(const float4*)(smem + (sRd - sbase) + (size_t)(i * SSTR) * 4);
                    float d;
                    d = xfA[i].x - mf.x; px = fmaf(d, d, px);
                    d = xfA[i].y - mf.y; px = fmaf(d, d, px);
                    d = xfA[i].z - mf.z; px = fmaf(d, d, px);
                    d = xfA[i].w - mf.w; px = fmaf(d, d, px);
                }
#pragma unroll
                for (int i = 0; i < 4; i++) {
                    float4 mf = *(const float4*)(smem + (sRd - sbase) + (size_t)((4 + i) * SSTR) * 4);
                    float d;
                    d = xfB[i].x - mf.x; px = fmaf(d, d, px);
                    d = xfB[i].y - mf.y; px = fmaf(d, d, px);
                    d = xfB[i].z - mf.z; px = fmaf(d, d, px);
                    d = xfB[i].w - mf.w; px = fmaf(d, d, px);
                }
            }
        }
    }
    __syncthreads();   // stage 1 done; smem pools reusable

    // ---- build stage-2 arrays ----
    float* zR = (float*)(smem + OFF_ZR);
    float* v1S = (float*)(smem + OFF_V1);
    float* qmS = (float*)(smem + OFF_QM);
    float* s2T = (float*)(smem + OFF_S2T);
    float* na2T = (float*)(smem + OFF_NA2T);
    float* compS = (float*)(smem + OFF_COMP);
    float* klzS = (float*)(smem + OFF_KLZ);

    for (int i = tid; i < ROWS * 32; i += THREADS) {
        const int r = i >> 5, zp = i & 31;
        const int gi = (rowbase + r) * ZD + 2 * zp;
        float2 qm2 = *(const float2*)(qmu + gi);
        float2 ql2 = *(const float2*)(qls + gi);
        float2 ep2 = *(const float2*)(eps + gi);
        float qs0 = expf(ql2.x), qs1 = expf(ql2.y);
        const int rb = r * RSTR + 2 * zp;
        *(float2*)(zR + rb) = make_float2(fmaf(qs0, ep2.x, qm2.x),
                                          fmaf(qs1, ep2.y, qm2.y));
        *(float2*)(v1S + rb) = make_float2(fmaf(qs0, qs0, qm2.x * qm2.x),
                                           fmaf(qs1, qs1, qm2.y * qm2.y));
        *(float2*)(qmS + rb) = qm2;
    }
    {
        const uint4* s1 = (const uint4*)g_s2T;
        const uint4* s2 = (const uint4*)g_na2T;
        uint4* d1 = (uint4*)s2T;
        uint4* d2 = (uint4*)na2T;
        for (int i = tid; i < (ZD * KK) / 4; i += THREADS) {
            d1[i] = s1[i];
            d2[i] = s2[i];
        }
    }
    __syncthreads();

    // ================= Stage 2a: quadratics, tile 2r x 8k, z-pairs ==========
    {
        const int tx = tid & 7, ty = tid >> 3;
        const int kb = 8 * tx, r0 = 2 * ty;
        ull accC[2][4], accK[2][4];
#pragma unroll
        for (int r = 0; r < 2; r++)
#pragma unroll
            for (int k = 0; k < 4; k++) { accC[r][k] = 0ull; accK[r][k] = 0ull; }

        const float* s2p = s2T + kb;
        const float* nap = na2T + kb;
        const int rb0 = r0 * RSTR, rb1 = rb0 + RSTR;
#pragma unroll 2
        for (int z = 0; z < ZD; z += 2) {
            ulonglong2 sA0 = *(const ulonglong2*)(s2p + z * KK);
            ulonglong2 sB0 = *(const ulonglong2*)(s2p + z * KK + 4);
            ulonglong2 nA0 = *(const ulonglong2*)(nap + z * KK);
            ulonglong2 nB0 = *(const ulonglong2*)(nap + z * KK + 4);
            ulonglong2 sA1 = *(const ulonglong2*)(s2p + (z + 1) * KK);
            ulonglong2 sB1 = *(const ulonglong2*)(s2p + (z + 1) * KK + 4);
            ulonglong2 nA1 = *(const ulonglong2*)(nap + (z + 1) * KK);
            ulonglong2 nB1 = *(const ulonglong2*)(nap + (z + 1) * KK + 4);
#pragma unroll
            for (int r = 0; r < 2; r++) {
                const int rb = (r ? rb1 : rb0) + z;
                float2 zf = *(const float2*)(zR + rb);
                float2 vf = *(const float2*)(v1S + rb);
                float2 qf = *(const float2*)(qmS + rb);
                ull zd = dup2(zf.x), vd = dup2(vf.x), qd = dup2(qf.x);
                ull t;
                t = fma2o(sA0.x, zd, nA0.x); accC[r][0] = fma2o(t, zd, accC[r][0]);
                t = fma2o(sA0.y, zd, nA0.y); accC[r][1] = fma2o(t, zd, accC[r][1]);
                t = fma2o(sB0.x, zd, nB0.x); accC[r][2] = fma2o(t, zd, accC[r][2]);
                t = fma2o(sB0.y, zd, nB0.y); accC[r][3] = fma2o(t, zd, accC[r][3]);
                accK[r][0] = fma2o(sA0.x, vd, accK[r][0]);
                accK[r][0] = fma2o(nA0.x, qd, accK[r][0]);
                accK[r][1] = fma2o(sA0.y, vd, accK[r][1]);
                accK[r][1] = fma2o(nA0.y, qd, accK[r][1]);
                accK[r][2] = fma2o(sB0.x, vd, accK[r][2]);
                accK[r][2] = fma2o(nB0.x, qd, accK[r][2]);
                accK[r][3] = fma2o(sB0.y, vd, accK[r][3]);
                accK[r][3] = fma2o(nB0.y, qd, accK[r][3]);
                zd = dup2(zf.y); vd = dup2(vf.y); qd = dup2(qf.y);
                t = fma2o(sA1.x, zd, nA1.x); accC[r][0] = fma2o(t, zd, accC[r][0]);
                t = fma2o(sA1.y, zd, nA1.y); accC[r][1] = fma2o(t, zd, accC[r][1]);
                t = fma2o(sB1.x, zd, nB1.x); accC[r][2] = fma2o(t, zd, accC[r][2]);
                t = fma2o(sB1.y, zd, nB1.y); accC[r][3] = fma2o(t, zd, accC[r][3]);
                accK[r][0] = fma2o(sA1.x, vd, accK[r][0]);
                accK[r][0] = fma2o(nA1.x, qd, accK[r][0]);
                accK[r][1] = fma2o(sA1.y, vd, accK[r][1]);
                accK[r][1] = fma2o(nA1.y, qd, accK[r][1]);
                accK[r][2] = fma2o(sB1.x, vd, accK[r][2]);
                accK[r][2] = fma2o(nB1.x, qd, accK[r][2]);
                accK[r][3] = fma2o(sB1.y, vd, accK[r][3]);
                accK[r][3] = fma2o(nB1.y, qd, accK[r][3]);
            }
        }
        float cc[8], ck[8];
        *(float4*)cc = *(const float4*)(g_cc2 + kb);
        *(float4*)(cc + 4) = *(const float4*)(g_cc2 + kb + 4);
        *(float4*)ck = *(const float4*)(g_ck2 + kb);
        *(float4*)(ck + 4) = *(const float4*)(g_ck2 + kb + 4);
#pragma unroll
        for (int r = 0; r < 2; r++) {
#pragma unroll
            for (int k = 0; k < 4; k++) {
                float lo, hi;
                unpack2(accC[r][k], lo, hi);
                *(float2*)(compS + (r0 + r) * KK + kb + 2 * k) =
                    make_float2(fmaf(-0.5f, lo, cc[2 * k]), fmaf(-0.5f, hi, cc[2 * k + 1]));
                unpack2(accK[r][k], lo, hi);
                *(float2*)(klzS + (r0 + r) * KK + kb + 2 * k) =
                    make_float2(fmaf(0.5f, lo, ck[2 * k]), fmaf(0.5f, hi, ck[2 * k + 1]));
            }
        }
    }
    __syncthreads();

    // ================= Stage 2b: softmax / KL (warp per row) =========
    float kl_acc = 0.f;
    for (int rr = 0; rr < 8; rr++) {
        const int r = wid + 16 * rr;
        const int grow = rowbase + r;
        float c0 = compS[r * KK + lane];
        float c1 = compS[r * KK + lane + 32];
        float k0 = klzS[r * KK + lane];
        float k1 = klzS[r * KK + lane + 32];
        float lp0 = logf(pi[grow * KK + lane]);
        float lp1 = logf(pi[grow * KK + lane + 32]);
        float q0 = qls[grow * ZD + lane];
        float q1 = qls[grow * ZD + lane + 32];

        float qsum = q0 + q1;
#pragma unroll
        for (int o = 16; o; o >>= 1) qsum += __shfl_xor_sync(~0u, qsum, o);
        float p0 = c0 + lp0, p1 = c1 + lp1;
        float m = fmaxf(p0, p1);
#pragma unroll
        for (int o = 16; o; o >>= 1) m = fmaxf(m, __shfl_xor_sync(~0u, m, o));
        float e0 = expf(p0 - m), e1 = expf(p1 - m);
        float es = e0 + e1;
#pragma unroll
        for (int o = 16; o; o >>= 1) es += __shfl_xor_sync(~0u, es, o);
        float lse = m + logf(es);
        float inv = 1.f / es;
        float pr0 = e0 * inv, pr1 = e1 * inv;
        float contrib = pr0 * (c0 - lse) + pr1 * (c1 - lse)
                      + pr0 * (k0 - qsum - 32.f) + pr1 * (k1 - qsum - 32.f);
#pragma unroll
        for (int o = 16; o; o >>= 1) contrib += __shfl_xor_sync(~0u, contrib, o);
        if (lane == 0) kl_acc += contrib;
    }

    // ---- deterministic block + grid reduction (fixed-point atomics) ----
    float pxw = px;
#pragma unroll
    for (int o = 16; o; o >>= 1) pxw += __shfl_xor_sync(~0u, pxw, o);
    if (lane == 0) { red[wid] = pxw; red[16 + wid] = kl_acc; }
    __syncthreads();
    if (tid == 0) {
        float sp = 0.f, sk = 0.f;
#pragma unroll
        for (int w = 0; w < 16; w++) { sp += red[w]; sk += red[16 + w]; }
        const double part = (double)(-0.5f * sp - sk);
        const long long q = llrint(part * FIXSCALE);
        atomicAdd(&g_acc, (ull)q);
        __threadfence();
        const unsigned t = atomicAdd(&g_cnt, 1u);
        if (t == NBLK - 1) {
            const long long tot = (long long)atomicAdd(&g_acc, 0ull);
            out[0] = (float)((double)tot / FIXSCALE / 16384.0
                             - 0.5 * LOG2PI * (double)XD);
            g_cnt = 0u;
            g_acc = 0ull;
        }
    }
}

extern "C" void kernel_launch(void* const* d_in, const int* in_sizes, int n_in,
                              void* d_out, int out_size) {
    (void)in_sizes; (void)n_in; (void)out_size;
    const float* x    = (const float*)d_in[0];
    const float* pi   = (const float*)d_in[1];
    const float* qmu  = (const float*)d_in[2];
    const float* qls  = (const float*)d_in[3];
    const float* eps  = (const float*)d_in[4];
    const float* pmu  = (const float*)d_in[5];
    const float* pls  = (const float*)d_in[6];
    const float* W    = (const float*)d_in[7];
    const float* bdec = (const float*)d_in[8];

    cudaFuncSetAttribute(main_kernel, cudaFuncAttributeMaxDynamicSharedMemorySize,
                         SMEM_BYTES);
    prep_kernel<<<15, 256>>>(W, pmu, pls);
    main_kernel<<<NBLK, THREADS, SMEM_BYTES>>>(x, pi, qmu, qls, eps, bdec,
                                               (float*)d_out);
}

// round 11
// speedup vs baseline: 1.3587x; 1.3587x over previous
#include <cuda_runtime.h>
#include <cuda_bf16.h>
#include <cstdint>

// GMMVAE ELBO. Stage1: z@W^T mma.sync bf16; x streamed via cp.async double
// buffer (guaranteed MLP). Stage2 f32x2. Fixed-point single-pass finish.
typedef unsigned long long ull;

#define B_TOT 16384
#define XD 784
#define ZD 64
#define KK 64
#define ROWS 128
#define THREADS 256
#define NBLK (B_TOT / ROWS)   // 128
#define NSLAB 14              // 14 x 56 cols
#define SLABP 60              // slab row stride (floats)
#define SLABB 30720           // slab bytes (128*60*4)
#define RSTR 66
#define LOG2PI 1.8378770664093453
#define FIXSCALE 262144.0

__device__ float g_s2T[ZD * KK];
__device__ float g_na2T[ZD * KK];
__device__ float g_cc2[KK];
__device__ float g_ck2[KK];
__device__ ull g_acc;
__device__ unsigned g_cnt;
__device__ __align__(16) __nv_bfloat16 g_Wt[XD * 64];  // [c][z] 128B swizzled rows

// ---- smem byte offsets ----
#define OFF_RED   0        // 128
#define OFF_BIAS  128      // 3136 -> 3264
#define OFF_ZBF   3328     // 16384 -> 19712
#define OFF_WT    19712    // 100352 -> 120064
#define OFF_XS    120064   // 2*30720 -> 181504
// post-stage1 overlays:
#define OFF_ZR    128      // 33792 -> 33920
#define OFF_V1    33920    // -> 67712
#define OFF_QM    67712    // -> 101504
#define OFF_S2T   101504   // -> 117888
#define OFF_NA2T  117888   // -> 134272
#define OFF_COMP  134272   // -> 167040
#define OFF_KLZ   167040   // -> 199808
#define SMEM_BYTES 199808

__device__ __forceinline__ uint32_t smem_u32(const void* p) {
    uint32_t a;
    asm("{ .reg .u64 t; cvta.to.shared.u64 t, %1; cvt.u32.u64 %0, t; }" : "=r"(a) : "l"(p));
    return a;
}
__device__ __forceinline__ ull fma2o(ull a, ull b, ull c) {
    ull d;
    asm("fma.rn.f32x2 %0, %1, %2, %3;" : "=l"(d) : "l"(a), "l"(b), "l"(c));
    return d;
}
__device__ __forceinline__ ull dup2(float x) {
    ull r;
    asm("mov.b64 %0, {%1, %1};" : "=l"(r) : "f"(x));
    return r;
}
__device__ __forceinline__ void unpack2(ull v, float& lo, float& hi) {
    asm("mov.b64 {%0, %1}, %2;" : "=f"(lo), "=f"(hi) : "l"(v));
}
__device__ __forceinline__ void ldm_x4(uint32_t& r0, uint32_t& r1, uint32_t& r2,
                                       uint32_t& r3, uint32_t addr) {
    asm volatile("ldmatrix.sync.aligned.m8n8.x4.shared.b16 {%0,%1,%2,%3}, [%4];"
                 : "=r"(r0), "=r"(r1), "=r"(r2), "=r"(r3) : "r"(addr));
}
__device__ __forceinline__ void mma_bf16(float& c0, float& c1, float& c2, float& c3,
                                         uint32_t a0, uint32_t a1, uint32_t a2, uint32_t a3,
                                         uint32_t b0, uint32_t b1) {
    asm volatile("mma.sync.aligned.m16n8k16.row.col.f32.bf16.bf16.f32 "
                 "{%0,%1,%2,%3}, {%4,%5,%6,%7}, {%8,%9}, {%0,%1,%2,%3};"
                 : "+f"(c0), "+f"(c1), "+f"(c2), "+f"(c3)
                 : "r"(a0), "r"(a1), "r"(a2), "r"(a3), "r"(b0), "r"(b1));
}
__device__ __forceinline__ uint32_t swz(int r, int zp) {
    return (uint32_t)(r * 128 + (((zp >> 2) ^ (r & 7)) << 4) + 4 * (zp & 3));
}
__device__ __forceinline__ void cpasync16(uint32_t dst, const float* src) {
    asm volatile("{ .reg .u64 g; cvta.to.global.u64 g, %1;\n\t"
                 "cp.async.cg.shared.global [%0], [g], 16; }"
                 :: "r"(dst), "l"(src) : "memory");
}
#define CP_COMMIT() asm volatile("cp.async.commit_group;" ::: "memory")
#define CP_WAIT1()  asm volatile("cp.async.wait_group 1;" ::: "memory")

// ======================= prep kernel (grid 15) =======================
__global__ void prep_kernel(const float* __restrict__ W,
                            const float* __restrict__ pmu,
                            const float* __restrict__ pls) {
    const int b = blockIdx.x, tid = threadIdx.x;
    if (b < 14) {
        __shared__ float sc[64 * 57];
        const int c0 = b * 56;
        for (int i = tid; i < 64 * 56; i += 256) {
            const int z = i / 56, c = i - z * 56;
            sc[z * 57 + c] = W[z * XD + c0 + c];
        }
        __syncthreads();
        for (int i = tid; i < 56 * 32; i += 256) {
            const int c = i >> 5, zp = i & 31;
            __nv_bfloat162 bv = __floats2bfloat162_rn(sc[(2 * zp) * 57 + c],
                                                      sc[(2 * zp + 1) * 57 + c]);
            *(uint32_t*)((char*)g_Wt + swz(c0 + c, zp)) = *(uint32_t*)&bv;
        }
    } else {
        const int k = tid >> 2, q = tid & 3;
        float lsum = 0.f, c1 = 0.f;
#pragma unroll
        for (int i = 0; i < 16; i++) {
            const int z = 16 * q + i;
            float ls = pls[k * ZD + z];
            float mu = pmu[k * ZD + z];
            float s2i = expf(-2.f * ls);
            g_s2T[z * KK + k] = s2i;
            g_na2T[z * KK + k] = -2.f * mu * s2i;
            lsum += ls;
            c1 = fmaf(mu * mu, s2i, c1);
        }
#pragma unroll
        for (int o = 1; o < 4; o <<= 1) {
            lsum += __shfl_xor_sync(~0u, lsum, o);
            c1 += __shfl_xor_sync(~0u, c1, o);
        }
        if (q == 0) {
            g_cc2[k] = (float)(-(double)lsum - 32.0 * LOG2PI - 0.5 * (double)c1);
            g_ck2[k] = lsum + 0.5f * c1;
        }
        if (tid == 0) { g_acc = 0ull; g_cnt = 0u; }
    }
}

// ======================= main kernel =======================
extern __shared__ char smem[];

__global__ __launch_bounds__(THREADS, 1)
void main_kernel(const float* __restrict__ x, const float* __restrict__ pi,
                 const float* __restrict__ qmu, const float* __restrict__ qls,
                 const float* __restrict__ eps, const float* __restrict__ bdec,
                 float* __restrict__ out) {
    const int tid = threadIdx.x;
    const int wid = tid >> 5, lane = tid & 31;
    const int rowbase = blockIdx.x * ROWS;
    const uint32_t sbase = smem_u32(smem);
    float* red = (float*)(smem + OFF_RED);
    float* biasS = (float*)(smem + OFF_BIAS);

    // ---- cp.async slab mapping (7 ops of 16B per thread) ----
    uint32_t xdst[7];
    size_t xsoff[7];
#pragma unroll
    for (int i = 0; i < 7; i++) {
        const int idx = tid + 256 * i;
        const int row = idx / 14, c4 = idx - row * 14;
        xdst[i] = sbase + OFF_XS + (uint32_t)(row * SLABP + 4 * c4) * 4;
        xsoff[i] = (size_t)(rowbase + row) * XD + 4 * c4;
    }
#define ISSUE_SLAB(s, buf) do {                                                \
    _Pragma("unroll")                                                          \
    for (int i_ = 0; i_ < 7; i_++)                                             \
        cpasync16(xdst[i_] + (buf) * SLABB, x + xsoff[i_] + 56 * (s));         \
} while (0)

    ISSUE_SLAB(0, 0);
    CP_COMMIT();
    ISSUE_SLAB(1, 1);
    CP_COMMIT();

    // ---- init: Wt copy, bias, z bf16 (A operand) ----
    {
        const uint4* src = (const uint4*)g_Wt;
        uint4* dst = (uint4*)(smem + OFF_WT);
        for (int i = tid; i < (XD * 128) / 16; i += THREADS) dst[i] = src[i];
    }
    for (int i = tid; i < XD; i += THREADS) biasS[i] = bdec[i];
    for (int i = tid; i < ROWS * 32; i += THREADS) {
        const int r = i >> 5, zp = i & 31;
        const int gi = (rowbase + r) * ZD + 2 * zp;
        float2 qm2 = *(const float2*)(qmu + gi);
        float2 ql2 = *(const float2*)(qls + gi);
        float2 ep2 = *(const float2*)(eps + gi);
        float z0 = fmaf(expf(ql2.x), ep2.x, qm2.x);
        float z1 = fmaf(expf(ql2.y), ep2.y, qm2.y);
        __nv_bfloat162 bv = __floats2bfloat162_rn(z0, z1);
        *(uint32_t*)(smem + OFF_ZBF + swz(r, zp)) = *(uint32_t*)&bv;
    }
    __syncthreads();

    // ================= Stage 1 =================
    float px = 0.f;
    {
        const int g = lane >> 3, lr = lane & 7;
        const int gx = g >> 1;
        const int mrow = 16 * wid;

        // A fragments (rows mrow..mrow+15, K=64)
        uint32_t a[16];
        {
            const int ra = mrow + lr + 8 * (g & 1);
            const uint32_t abase = sbase + OFF_ZBF + ra * 128;
#pragma unroll
            for (int kt = 0; kt < 4; kt++)
                ldm_x4(a[4 * kt], a[4 * kt + 1], a[4 * kt + 2], a[4 * kt + 3],
                       abase + (uint32_t)(((gx + 2 * kt) ^ (ra & 7)) << 4));
        }
        const uint32_t bb0 = sbase + OFF_WT + lr * 128 + (uint32_t)((g ^ lr) << 4);
        const uint32_t bb1 = sbase + OFF_WT + lr * 128 + (uint32_t)(((g + 4) ^ lr) << 4);
        const int fr0 = mrow + (lane >> 2);
        const int fcol = 2 * (lane & 3);

        for (int s = 0; s < NSLAB; s++) {
            CP_WAIT1();
            __syncthreads();   // slab s visible to all
            const float* xb = (const float*)(smem + OFF_XS + (s & 1) * SLABB);
#pragma unroll
            for (int lt = 0; lt < 7; lt++) {
                const int jt = 7 * s + lt;
                uint32_t b[8];
                const uint32_t toff = (uint32_t)jt * 1024;
                ldm_x4(b[0], b[1], b[2], b[3], bb0 + toff);
                ldm_x4(b[4], b[5], b[6], b[7], bb1 + toff);
                float c0 = 0.f, c1 = 0.f, c2 = 0.f, c3 = 0.f;
                float d0 = 0.f, d1 = 0.f, d2 = 0.f, d3 = 0.f;
                mma_bf16(c0, c1, c2, c3, a[0], a[1], a[2], a[3], b[0], b[1]);
                mma_bf16(d0, d1, d2, d3, a[8], a[9], a[10], a[11], b[4], b[5]);
                mma_bf16(c0, c1, c2, c3, a[4], a[5], a[6], a[7], b[2], b[3]);
                mma_bf16(d0, d1, d2, d3, a[12], a[13], a[14], a[15], b[6], b[7]);

                float2 bb = *(const float2*)(biasS + 8 * jt + fcol);
                float2 x0 = *(const float2*)(xb + fr0 * SLABP + 8 * lt + fcol);
                float2 x1 = *(const float2*)(xb + (fr0 + 8) * SLABP + 8 * lt + fcol);
                float d;
                d = x0.x - (c0 + d0 + bb.x); px = fmaf(d, d, px);
                d = x0.y - (c1 + d1 + bb.y); px = fmaf(d, d, px);
                d = x1.x - (c2 + d2 + bb.x); px = fmaf(d, d, px);
                d = x1.y - (c3 + d3 + bb.y); px = fmaf(d, d, px);
            }
            __syncthreads();   // all warps done reading buf before overwrite
            if (s + 2 < NSLAB) ISSUE_SLAB(s + 2, s & 1);
            CP_COMMIT();       // commit (possibly empty) keeps group count aligned
        }
    }
    __syncthreads();   // stage 1 done; smem pools reusable

    // ---- build stage-2 arrays ----
    float* zR = (float*)(smem + OFF_ZR);
    float* v1S = (float*)(smem + OFF_V1);
    float* qmS = (float*)(smem + OFF_QM);
    float* s2T = (float*)(smem + OFF_S2T);
    float* na2T = (float*)(smem + OFF_NA2T);
    float* compS = (float*)(smem + OFF_COMP);
    float* klzS = (float*)(smem + OFF_KLZ);

    for (int i = tid; i < ROWS * 32; i += THREADS) {
        const int r = i >> 5, zp = i & 31;
        const int gi = (rowbase + r) * ZD + 2 * zp;
        float2 qm2 = *(const float2*)(qmu + gi);
        float2 ql2 = *(const float2*)(qls + gi);
        float2 ep2 = *(const float2*)(eps + gi);
        float qs0 = expf(ql2.x), qs1 = expf(ql2.y);
        const int rb = r * RSTR + 2 * zp;
        *(float2*)(zR + rb) = make_float2(fmaf(qs0, ep2.x, qm2.x),
                                          fmaf(qs1, ep2.y, qm2.y));
        *(float2*)(v1S + rb) = make_float2(fmaf(qs0, qs0, qm2.x * qm2.x),
                                           fmaf(qs1, qs1, qm2.y * qm2.y));
        *(float2*)(qmS + rb) = qm2;
    }
    {
        const uint4* s1 = (const uint4*)g_s2T;
        const uint4* s2 = (const uint4*)g_na2T;
        uint4* d1 = (uint4*)s2T;
        uint4* d2 = (uint4*)na2T;
        for (int i = tid; i < (ZD * KK) / 4; i += THREADS) {
            d1[i] = s1[i];
            d2[i] = s2[i];
        }
    }
    __syncthreads();

    // ================= Stage 2a: quadratics, 2 passes of 2r x 8k ==========
    {
        const int tx = tid & 7, ty = tid >> 3;
        const int kb = 8 * tx;
        const float* s2p = s2T + kb;
        const float* nap = na2T + kb;
        float cc[8], ck[8];
        *(float4*)cc = *(const float4*)(g_cc2 + kb);
        *(float4*)(cc + 4) = *(const float4*)(g_cc2 + kb + 4);
        *(float4*)ck = *(const float4*)(g_ck2 + kb);
        *(float4*)(ck + 4) = *(const float4*)(g_ck2 + kb + 4);

#pragma unroll 1
        for (int pass = 0; pass < 2; pass++) {
            const int r0 = 2 * ty + 64 * pass;
            ull accC[2][4], accK[2][4];
#pragma unroll
            for (int r = 0; r < 2; r++)
#pragma unroll
                for (int k = 0; k < 4; k++) { accC[r][k] = 0ull; accK[r][k] = 0ull; }
            const int rb0 = r0 * RSTR, rb1 = rb0 + RSTR;
#pragma unroll 2
            for (int z = 0; z < ZD; z += 2) {
                ulonglong2 sA0 = *(const ulonglong2*)(s2p + z * KK);
                ulonglong2 sB0 = *(const ulonglong2*)(s2p + z * KK + 4);
                ulonglong2 nA0 = *(const ulonglong2*)(nap + z * KK);
                ulonglong2 nB0 = *(const ulonglong2*)(nap + z * KK + 4);
                ulonglong2 sA1 = *(const ulonglong2*)(s2p + (z + 1) * KK);
                ulonglong2 sB1 = *(const ulonglong2*)(s2p + (z + 1) * KK + 4);
                ulonglong2 nA1 = *(const ulonglong2*)(nap + (z + 1) * KK);
                ulonglong2 nB1 = *(const ulonglong2*)(nap + (z + 1) * KK + 4);
#pragma unroll
                for (int r = 0; r < 2; r++) {
                    const int rb = (r ? rb1 : rb0) + z;
                    float2 zf = *(const float2*)(zR + rb);
                    float2 vf = *(const float2*)(v1S + rb);
                    float2 qf = *(const float2*)(qmS + rb);
                    ull zd = dup2(zf.x), vd = dup2(vf.x), qd = dup2(qf.x);
                    ull t;
                    t = fma2o(sA0.x, zd, nA0.x); accC[r][0] = fma2o(t, zd, accC[r][0]);
                    t = fma2o(sA0.y, zd, nA0.y); accC[r][1] = fma2o(t, zd, accC[r][1]);
                    t = fma2o(sB0.x, zd, nB0.x); accC[r][2] = fma2o(t, zd, accC[r][2]);
                    t = fma2o(sB0.y, zd, nB0.y); accC[r][3] = fma2o(t, zd, accC[r][3]);
                    accK[r][0] = fma2o(sA0.x, vd, accK[r][0]);
                    accK[r][0] = fma2o(nA0.x, qd, accK[r][0]);
                    accK[r][1] = fma2o(sA0.y, vd, accK[r][1]);
                    accK[r][1] = fma2o(nA0.y, qd, accK[r][1]);
                    accK[r][2] = fma2o(sB0.x, vd, accK[r][2]);
                    accK[r][2] = fma2o(nB0.x, qd, accK[r][2]);
                    accK[r][3] = fma2o(sB0.y, vd, accK[r][3]);
                    accK[r][3] = fma2o(nB0.y, qd, accK[r][3]);
                    zd = dup2(zf.y); vd = dup2(vf.y); qd = dup2(qf.y);
                    t = fma2o(sA1.x, zd, nA1.x); accC[r][0] = fma2o(t, zd, accC[r][0]);
                    t = fma2o(sA1.y, zd, nA1.y); accC[r][1] = fma2o(t, zd, accC[r][1]);
                    t = fma2o(sB1.x, zd, nB1.x); accC[r][2] = fma2o(t, zd, accC[r][2]);
                    t = fma2o(sB1.y, zd, nB1.y); accC[r][3] = fma2o(t, zd, accC[r][3]);
                    accK[r][0] = fma2o(sA1.x, vd, accK[r][0]);
                    accK[r][0] = fma2o(nA1.x, qd, accK[r][0]);
                    accK[r][1] = fma2o(sA1.y, vd, accK[r][1]);
                    accK[r][1] = fma2o(nA1.y, qd, accK[r][1]);
                    accK[r][2] = fma2o(sB1.x, vd, accK[r][2]);
                    accK[r][2] = fma2o(nB1.x, qd, accK[r][2]);
                    accK[r][3] = fma2o(sB1.y, vd, accK[r][3]);
                    accK[r][3] = fma2o(nB1.y, qd, accK[r][3]);
                }
            }
#pragma unroll
            for (int r = 0; r < 2; r++) {
#pragma unroll
                for (int k = 0; k < 4; k++) {
                    float lo, hi;
                    unpack2(accC[r][k], lo, hi);
                    *(float2*)(compS + (r0 + r) * KK + kb + 2 * k) =
                        make_float2(fmaf(-0.5f, lo, cc[2 * k]),
                                    fmaf(-0.5f, hi, cc[2 * k + 1]));
                    unpack2(accK[r][k], lo, hi);
                    *(float2*)(klzS + (r0 + r) * KK + kb + 2 * k) =
                        make_float2(fmaf(0.5f, lo, ck[2 * k]),
                                    fmaf(0.5f, hi, ck[2 * k + 1]));
                }
            }
        }
    }
    __syncthreads();

    // ================= Stage 2b: softmax / KL (warp per row) =========
    float kl_acc = 0.f;
    for (int rr = 0; rr < 16; rr++) {
        const int r = wid + 8 * rr;
        const int grow = rowbase + r;
        float c0 = compS[r * KK + lane];
        float c1 = compS[r * KK + lane + 32];
        float k0 = klzS[r * KK + lane];
        float k1 = klzS[r * KK + lane + 32];
        float lp0 = logf(pi[grow * KK + lane]);
        float lp1 = logf(pi[grow * KK + lane + 32]);
        float q0 = qls[grow * ZD + lane];
        float q1 = qls[grow * ZD + lane + 32];

        float qsum = q0 + q1;
#pragma unroll
        for (int o = 16; o; o >>= 1) qsum += __shfl_xor_sync(~0u, qsum, o);
        float p0 = c0 + lp0, p1 = c1 + lp1;
        float m = fmaxf(p0, p1);
#pragma unroll
        for (int o = 16; o; o >>= 1) m = fmaxf(m, __shfl_xor_sync(~0u, m, o));
        float e0 = expf(p0 - m), e1 = expf(p1 - m);
        float es = e0 + e1;
#pragma unroll
        for (int o = 16; o; o >>= 1) es += __shfl_xor_sync(~0u, es, o);
        float lse = m + logf(es);
        float inv = 1.f / es;
        float pr0 = e0 * inv, pr1 = e1 * inv;
        float contrib = pr0 * (c0 - lse) + pr1 * (c1 - lse)
                      + pr0 * (k0 - qsum - 32.f) + pr1 * (k1 - qsum - 32.f);
#pragma unroll
        for (int o = 16; o; o >>= 1) contrib += __shfl_xor_sync(~0u, contrib, o);
        if (lane == 0) kl_acc += contrib;
    }

    // ---- deterministic block + grid reduction (fixed-point atomics) ----
    float pxw = px;
#pragma unroll
    for (int o = 16; o; o >>= 1) pxw += __shfl_xor_sync(~0u, pxw, o);
    if (lane == 0) { red[wid] = pxw; red[8 + wid] = kl_acc; }
    __syncthreads();
    if (tid == 0) {
        float sp = 0.f, sk = 0.f;
#pragma unroll
        for (int w = 0; w < 8; w++) { sp += red[w]; sk += red[8 + w]; }
        const double part = (double)(-0.5f * sp - sk);
        const long long q = llrint(part * FIXSCALE);
        atomicAdd(&g_acc, (ull)q);
        __threadfence();
        const unsigned t = atomicAdd(&g_cnt, 1u);
        if (t == NBLK - 1) {
            const long long tot = (long long)atomicAdd(&g_acc, 0ull);
            out[0] = (float)((double)tot / FIXSCALE / 16384.0
                             - 0.5 * LOG2PI * (double)XD);
            g_cnt = 0u;
            g_acc = 0ull;
        }
    }
}

extern "C" void kernel_launch(void* const* d_in, const int* in_sizes, int n_in,
                              void* d_out, int out_size) {
    (void)in_sizes; (void)n_in; (void)out_size;
    const float* x    = (const float*)d_in[0];
    const float* pi   = (const float*)d_in[1];
    const float* qmu  = (const float*)d_in[2];
    const float* qls  = (const float*)d_in[3];
    const float* eps  = (const float*)d_in[4];
    const float* pmu  = (const float*)d_in[5];
    const float* pls  = (const float*)d_in[6];
    const float* W    = (const float*)d_in[7];
    const float* bdec = (const float*)d_in[8];

    cudaFuncSetAttribute(main_kernel, cudaFuncAttributeMaxDynamicSharedMemorySize,
                         SMEM_BYTES);
    prep_kernel<<<15, 256>>>(W, pmu, pls);
    main_kernel<<<NBLK, THREADS, SMEM_BYTES>>>(x, pi, qmu, qls, eps, bdec,
                                               (float*)d_out);
}

// round 14
// speedup vs baseline: 1.8539x; 1.3645x over previous
#include <cuda_runtime.h>
#include <cuda_bf16.h>
#include <cstdint>

// GMMVAE ELBO, warp-specialized: warps 0-7 = mean GEMM + log_px (mma.sync bf16),
// warps 8-15 = mixture quadratics + in-register softmax/KL. No inter-stage sync.
typedef unsigned long long ull;

#define B_TOT 16384
#define XD 784
#define ZD 64
#define KK 64
#define ROWS 128
#define THREADS 512
#define NBLK (B_TOT / ROWS)   // 128
#define RSTR 66
#define LOG2PI 1.8378770664093453
#define FIXSCALE 262144.0

__device__ float g_s2T[ZD * KK];
__device__ float g_na2T[ZD * KK];
__device__ float g_cc2[KK];
__device__ float g_ck2[KK];
__device__ ull g_acc;
__device__ unsigned g_cnt;
__device__ __align__(16) __nv_bfloat16 g_Wt[XD * 64];  // [c][z] 128B swizzled rows

// ---- smem byte offsets ----
#define OFF_RED   0        // 16 floats
#define OFF_QSUM  128      // 128 floats -> 640
#define OFF_BIAS  640      // 784 f32 -> 3776
#define OFF_ZBF   3840     // 16384 -> 20224
#define OFF_WT    20224    // 50176 -> 70400  (half of W, reloaded)
#define OFF_ZR    70400    // 128*66*4 = 33792 -> 104192
#define OFF_V1    104192   // -> 137984
#define OFF_QM    137984   // -> 171776
#define OFF_S2T   171776   // 16384 -> 188160
#define OFF_NA2T  188160   // 16384 -> 204544
#define SMEM_BYTES 204544

__device__ __forceinline__ uint32_t smem_u32(const void* p) {
    uint32_t a;
    asm("{ .reg .u64 t; cvta.to.shared.u64 t, %1; cvt.u32.u64 %0, t; }" : "=r"(a) : "l"(p));
    return a;
}
__device__ __forceinline__ ull fma2o(ull a, ull b, ull c) {
    ull d;
    asm("fma.rn.f32x2 %0, %1, %2, %3;" : "=l"(d) : "l"(a), "l"(b), "l"(c));
    return d;
}
__device__ __forceinline__ ull dup2(float x) {
    ull r;
    asm("mov.b64 %0, {%1, %1};" : "=l"(r) : "f"(x));
    return r;
}
__device__ __forceinline__ void unpack2(ull v, float& lo, float& hi) {
    asm("mov.b64 {%0, %1}, %2;" : "=f"(lo), "=f"(hi) : "l"(v));
}
__device__ __forceinline__ void ldm_x4(uint32_t& r0, uint32_t& r1, uint32_t& r2,
                                       uint32_t& r3, uint32_t addr) {
    asm volatile("ldmatrix.sync.aligned.m8n8.x4.shared.b16 {%0,%1,%2,%3}, [%4];"
                 : "=r"(r0), "=r"(r1), "=r"(r2), "=r"(r3) : "r"(addr));
}
__device__ __forceinline__ void mma_bf16(float& c0, float& c1, float& c2, float& c3,
                                         uint32_t a0, uint32_t a1, uint32_t a2, uint32_t a3,
                                         uint32_t b0, uint32_t b1) {
    asm volatile("mma.sync.aligned.m16n8k16.row.col.f32.bf16.bf16.f32 "
                 "{%0,%1,%2,%3}, {%4,%5,%6,%7}, {%8,%9}, {%0,%1,%2,%3};"
                 : "+f"(c0), "+f"(c1), "+f"(c2), "+f"(c3)
                 : "r"(a0), "r"(a1), "r"(a2), "r"(a3), "r"(b0), "r"(b1));
}
__device__ __forceinline__ uint32_t swz(int r, int zp) {
    return (uint32_t)(r * 128 + (((zp >> 2) ^ (r & 7)) << 4) + 4 * (zp & 3));
}

// ======================= prep kernel (grid 15) =======================
__global__ void prep_kernel(const float* __restrict__ W,
                            const float* __restrict__ pmu,
                            const float* __restrict__ pls) {
    const int b = blockIdx.x, tid = threadIdx.x;
    if (b < 14) {
        __shared__ float sc[64 * 57];
        const int c0 = b * 56;
        for (int i = tid; i < 64 * 56; i += 256) {
            const int z = i / 56, c = i - z * 56;
            sc[z * 57 + c] = W[z * XD + c0 + c];
        }
        __syncthreads();
        for (int i = tid; i < 56 * 32; i += 256) {
            const int c = i >> 5, zp = i & 31;
            __nv_bfloat162 bv = __floats2bfloat162_rn(sc[(2 * zp) * 57 + c],
                                                      sc[(2 * zp + 1) * 57 + c]);
            *(uint32_t*)((char*)g_Wt + swz(c0 + c, zp)) = *(uint32_t*)&bv;
        }
    } else {
        const int k = tid >> 2, q = tid & 3;
        float lsum = 0.f, c1 = 0.f;
#pragma unroll
        for (int i = 0; i < 16; i++) {
            const int z = 16 * q + i;
            float ls = pls[k * ZD + z];
            float mu = pmu[k * ZD + z];
            float s2i = expf(-2.f * ls);
            g_s2T[z * KK + k] = s2i;
            g_na2T[z * KK + k] = -2.f * mu * s2i;
            lsum += ls;
            c1 = fmaf(mu * mu, s2i, c1);
        }
#pragma unroll
        for (int o = 1; o < 4; o <<= 1) {
            lsum += __shfl_xor_sync(~0u, lsum, o);
            c1 += __shfl_xor_sync(~0u, c1, o);
        }
        if (q == 0) {
            g_cc2[k] = (float)(-(double)lsum - 32.0 * LOG2PI - 0.5 * (double)c1);
            g_ck2[k] = lsum + 0.5f * c1;
        }
        if (tid == 0) { g_acc = 0ull; g_cnt = 0u; }
    }
}

// ======================= main kernel =======================
extern __shared__ char smem[];

#define LDB(dst, t) do {                                                       \
    const uint32_t bt_ = (uint32_t)(t) * 1024;                                 \
    ldm_x4((dst)[0], (dst)[1], (dst)[2], (dst)[3], bb0 + bt_);                 \
    ldm_x4((dst)[4], (dst)[5], (dst)[6], (dst)[7], bb1 + bt_);                 \
} while (0)

#define LDXS(xa, xb, bb, t) do {                                               \
    const int co_ = c0 + 8 * (t);                                              \
    bb = *(const float2*)(biasS + co_ + fcol);                                 \
    xa = *(const float2*)(pxA + co_);                                          \
    xb = *(const float2*)(pxB + co_);                                          \
} while (0)

#define TILE_BODY(bf, xa, xb, bb) do {                                         \
    float cA0 = 0.f, cA1 = 0.f, cA2 = 0.f, cA3 = 0.f;                          \
    float cB0 = 0.f, cB1 = 0.f, cB2 = 0.f, cB3 = 0.f;                          \
    mma_bf16(cA0, cA1, cA2, cA3, a[0], a[1], a[2], a[3], (bf)[0], (bf)[1]);    \
    mma_bf16(cB0, cB1, cB2, cB3, a[8], a[9], a[10], a[11], (bf)[4], (bf)[5]);  \
    mma_bf16(cA0, cA1, cA2, cA3, a[4], a[5], a[6], a[7], (bf)[2], (bf)[3]);    \
    mma_bf16(cB0, cB1, cB2, cB3, a[12], a[13], a[14], a[15], (bf)[6], (bf)[7]);\
    float d_;                                                                  \
    d_ = ((xa).x - (bb).x) - (cA0 + cB0); px = fmaf(d_, d_, px);               \
    d_ = ((xa).y - (bb).y) - (cA1 + cB1); px = fmaf(d_, d_, px);               \
    d_ = ((xb).x - (bb).x) - (cA2 + cB2); px = fmaf(d_, d_, px);               \
    d_ = ((xb).y - (bb).y) - (cA3 + cB3); px = fmaf(d_, d_, px);               \
} while (0)

__global__ __launch_bounds__(THREADS, 1)
void main_kernel(const float* __restrict__ x, const float* __restrict__ pi,
                 const float* __restrict__ qmu, const float* __restrict__ qls,
                 const float* __restrict__ eps, const float* __restrict__ bdec,
                 float* __restrict__ out) {
    const int tid = threadIdx.x;
    const int wid = tid >> 5, lane = tid & 31;
    const int rowbase = blockIdx.x * ROWS;
    const uint32_t sbase = smem_u32(smem);
    float* red = (float*)(smem + OFF_RED);
    float* qsumS = (float*)(smem + OFF_QSUM);
    float* biasS = (float*)(smem + OFF_BIAS);
    float* zR = (float*)(smem + OFF_ZR);
    float* v1S = (float*)(smem + OFF_V1);
    float* qmS = (float*)(smem + OFF_QM);
    float* s2T = (float*)(smem + OFF_S2T);
    float* na2T = (float*)(smem + OFF_NA2T);

    // ---- init: W half 0, per-k tables, bias, z/v1/qm/qsum build ----
    {
        const uint4* src = (const uint4*)g_Wt;
        uint4* dst = (uint4*)(smem + OFF_WT);
        for (int i = tid; i < 3136; i += THREADS) dst[i] = src[i];
        const uint4* s1 = (const uint4*)g_s2T;
        const uint4* s2 = (const uint4*)g_na2T;
        uint4* d1 = (uint4*)s2T;
        uint4* d2 = (uint4*)na2T;
        for (int i = tid; i < (ZD * KK) / 4; i += THREADS) {
            d1[i] = s1[i];
            d2[i] = s2[i];
        }
    }
    for (int i = tid; i < XD; i += THREADS) biasS[i] = bdec[i];
#pragma unroll
    for (int k = 0; k < 8; k++) {
        const int i = tid + THREADS * k;      // row = wid + 16k, zp = lane
        const int r = i >> 5, zp = i & 31;
        const int gi = (rowbase + r) * ZD + 2 * zp;
        float2 qm2 = *(const float2*)(qmu + gi);
        float2 ql2 = *(const float2*)(qls + gi);
        float2 ep2 = *(const float2*)(eps + gi);
        float qs0 = expf(ql2.x), qs1 = expf(ql2.y);
        float z0 = fmaf(qs0, ep2.x, qm2.x);
        float z1 = fmaf(qs1, ep2.y, qm2.y);
        __nv_bfloat162 bv = __floats2bfloat162_rn(z0, z1);
        *(uint32_t*)(smem + OFF_ZBF + swz(r, zp)) = *(uint32_t*)&bv;
        const int rb = r * RSTR + 2 * zp;
        *(float2*)(zR + rb) = make_float2(z0, z1);
        *(float2*)(v1S + rb) = make_float2(fmaf(qs0, qs0, qm2.x * qm2.x),
                                           fmaf(qs1, qs1, qm2.y * qm2.y));
        *(float2*)(qmS + rb) = qm2;
        float qs = ql2.x + ql2.y;             // row-sum of qls via warp reduce
#pragma unroll
        for (int o = 16; o; o >>= 1) qs += __shfl_xor_sync(~0u, qs, o);
        if (lane == 0) qsumS[r] = qs;
    }
    __syncthreads();

    if (wid < 8) {
        // ================= Stage 1: mean GEMM + log_px (warps 0-7) ==========
        float px = 0.f;
        const int g = lane >> 3, lr = lane & 7, gx = g >> 1;
        const int mrow = 16 * wid;
        uint32_t a[16];
        {
            const int ra = mrow + lr + 8 * (g & 1);
            const uint32_t abase = sbase + OFF_ZBF + ra * 128;
#pragma unroll
            for (int kt = 0; kt < 4; kt++)
                ldm_x4(a[4 * kt], a[4 * kt + 1], a[4 * kt + 2], a[4 * kt + 3],
                       abase + (uint32_t)(((gx + 2 * kt) ^ (ra & 7)) << 4));
        }
        const uint32_t bb0 = sbase + OFF_WT + lr * 128 + (uint32_t)((g ^ lr) << 4);
        const uint32_t bb1 = sbase + OFF_WT + lr * 128 + (uint32_t)(((g + 4) ^ lr) << 4);
        const float* pxA = x + (size_t)(rowbase + mrow + (lane >> 2)) * XD + 2 * (lane & 3);
        const float* pxB = pxA + 8 * XD;
        const int fcol = 2 * (lane & 3);

#pragma unroll 1
        for (int h = 0; h < 2; h++) {
            if (h) {
                asm volatile("bar.sync 1, 256;" ::: "memory");
                const uint4* src = (const uint4*)((const char*)g_Wt + 50176);
                uint4* dst = (uint4*)(smem + OFF_WT);
                for (int i = tid; i < 3136; i += 256) dst[i] = src[i];
                asm volatile("bar.sync 1, 256;" ::: "memory");
            }
            const int c0 = 392 * h;
            uint32_t b0[8], b1[8];
            float2 xaA, xbA, bbA, xaB, xbB, bbB;
            LDB(b0, 0);
            LDXS(xaA, xbA, bbA, 0);
            for (int t = 1; t < 49; t += 2) {
                LDB(b1, t);
                LDXS(xaB, xbB, bbB, t);
                TILE_BODY(b0, xaA, xbA, bbA);
                LDB(b0, t + 1);
                LDXS(xaA, xbA, bbA, t + 1);
                TILE_BODY(b1, xaB, xbB, bbB);
            }
            TILE_BODY(b0, xaA, xbA, bbA);
        }
#pragma unroll
        for (int o = 16; o; o >>= 1) px += __shfl_xor_sync(~0u, px, o);
        if (lane == 0) red[wid] = px;
    } else {
        // ============ Stage 2 (warps 8-15): quadratics + in-reg softmax =====
        const int st = tid - 256;
        const int tx = st & 7, ty = st >> 3;
        const int kb = 8 * tx;
        const float* s2p = s2T + kb;
        const float* nap = na2T + kb;
        float cc[8], ck[8];
        *(float4*)cc = *(const float4*)(g_cc2 + kb);
        *(float4*)(cc + 4) = *(const float4*)(g_cc2 + kb + 4);
        *(float4*)ck = *(const float4*)(g_ck2 + kb);
        *(float4*)(ck + 4) = *(const float4*)(g_ck2 + kb + 4);
        float kl_acc = 0.f;

#pragma unroll 1
        for (int pass = 0; pass < 2; pass++) {
            const int r0 = 2 * ty + 64 * pass;
            ull accC[2][4], accK[2][4];
#pragma unroll
            for (int r = 0; r < 2; r++)
#pragma unroll
                for (int k = 0; k < 4; k++) { accC[r][k] = 0ull; accK[r][k] = 0ull; }
            const int rb0 = r0 * RSTR, rb1 = rb0 + RSTR;
#pragma unroll 2
            for (int z = 0; z < ZD; z += 2) {
                ulonglong2 sA0 = *(const ulonglong2*)(s2p + z * KK);
                ulonglong2 sB0 = *(const ulonglong2*)(s2p + z * KK + 4);
                ulonglong2 nA0 = *(const ulonglong2*)(nap + z * KK);
                ulonglong2 nB0 = *(const ulonglong2*)(nap + z * KK + 4);
                ulonglong2 sA1 = *(const ulonglong2*)(s2p + (z + 1) * KK);
                ulonglong2 sB1 = *(const ulonglong2*)(s2p + (z + 1) * KK + 4);
                ulonglong2 nA1 = *(const ulonglong2*)(nap + (z + 1) * KK);
                ulonglong2 nB1 = *(const ulonglong2*)(nap + (z + 1) * KK + 4);
#pragma unroll
                for (int r = 0; r < 2; r++) {
                    const int rb = (r ? rb1 : rb0) + z;
                    float2 zf = *(const float2*)(zR + rb);
                    float2 vf = *(const float2*)(v1S + rb);
                    float2 qf = *(const float2*)(qmS + rb);
                    ull zd = dup2(zf.x), vd = dup2(vf.x), qd = dup2(qf.x);
                    ull t;
                    t = fma2o(sA0.x, zd, nA0.x); accC[r][0] = fma2o(t, zd, accC[r][0]);
                    t = fma2o(sA0.y, zd, nA0.y); accC[r][1] = fma2o(t, zd, accC[r][1]);
                    t = fma2o(sB0.x, zd, nB0.x); accC[r][2] = fma2o(t, zd, accC[r][2]);
                    t = fma2o(sB0.y, zd, nB0.y); accC[r][3] = fma2o(t, zd, accC[r][3]);
                    accK[r][0] = fma2o(sA0.x, vd, accK[r][0]);
                    accK[r][0] = fma2o(nA0.x, qd, accK[r][0]);
                    accK[r][1] = fma2o(sA0.y, vd, accK[r][1]);
                    accK[r][1] = fma2o(nA0.y, qd, accK[r][1]);
                    accK[r][2] = fma2o(sB0.x, vd, accK[r][2]);
                    accK[r][2] = fma2o(nB0.x, qd, accK[r][2]);
                    accK[r][3] = fma2o(sB0.y, vd, accK[r][3]);
                    accK[r][3] = fma2o(nB0.y, qd, accK[r][3]);
                    zd = dup2(zf.y); vd = dup2(vf.y); qd = dup2(qf.y);
                    t = fma2o(sA1.x, zd, nA1.x); accC[r][0] = fma2o(t, zd, accC[r][0]);
                    t = fma2o(sA1.y, zd, nA1.y); accC[r][1] = fma2o(t, zd, accC[r][1]);
                    t = fma2o(sB1.x, zd, nB1.x); accC[r][2] = fma2o(t, zd, accC[r][2]);
                    t = fma2o(sB1.y, zd, nB1.y); accC[r][3] = fma2o(t, zd, accC[r][3]);
                    accK[r][0] = fma2o(sA1.x, vd, accK[r][0]);
                    accK[r][0] = fma2o(nA1.x, qd, accK[r][0]);
                    accK[r][1] = fma2o(sA1.y, vd, accK[r][1]);
                    accK[r][1] = fma2o(nA1.y, qd, accK[r][1]);
                    accK[r][2] = fma2o(sB1.x, vd, accK[r][2]);
                    accK[r][2] = fma2o(nB1.x, qd, accK[r][2]);
                    accK[r][3] = fma2o(sB1.y, vd, accK[r][3]);
                    accK[r][3] = fma2o(nB1.y, qd, accK[r][3]);
                }
            }
            // ---- fused softmax/KL: row's 64 k live in the 8-lane group ----
#pragma unroll
            for (int r = 0; r < 2; r++) {
                float comp[8], klz[8];
#pragma unroll
                for (int q = 0; q < 4; q++) {
                    float lo, hi;
                    unpack2(accC[r][q], lo, hi);
                    comp[2 * q] = fmaf(-0.5f, lo, cc[2 * q]);
                    comp[2 * q + 1] = fmaf(-0.5f, hi, cc[2 * q + 1]);
                    unpack2(accK[r][q], lo, hi);
                    klz[2 * q] = fmaf(0.5f, lo, ck[2 * q]);
                    klz[2 * q + 1] = fmaf(0.5f, hi, ck[2 * q + 1]);
                }
                const int rl = r0 + r;
                const float* pip = pi + (size_t)(rowbase + rl) * KK + kb;
                float4 pa = *(const float4*)pip;
                float4 pb = *(const float4*)(pip + 4);
                float lp[8];
                lp[0] = __logf(pa.x); lp[1] = __logf(pa.y);
                lp[2] = __logf(pa.z); lp[3] = __logf(pa.w);
                lp[4] = __logf(pb.x); lp[5] = __logf(pb.y);
                lp[6] = __logf(pb.z); lp[7] = __logf(pb.w);
                float p[8], m = -1e30f;
#pragma unroll
                for (int j = 0; j < 8; j++) { p[j] = comp[j] + lp[j]; m = fmaxf(m, p[j]); }
#pragma unroll
                for (int o = 1; o < 8; o <<= 1) m = fmaxf(m, __shfl_xor_sync(~0u, m, o));
                float e[8], es = 0.f;
#pragma unroll
                for (int j = 0; j < 8; j++) { e[j] = __expf(p[j] - m); es += e[j]; }
#pragma unroll
                for (int o = 1; o < 8; o <<= 1) es += __shfl_xor_sync(~0u, es, o);
                const float lse = m + __logf(es);
                const float inv = 1.f / es;
                const float klf = qsumS[rl] + 32.f + lse;   // subtractive constant
                float ctr = 0.f;
#pragma unroll
                for (int j = 0; j < 8; j++)
                    ctr = fmaf(e[j], (comp[j] - lse) + (klz[j] - klf + lse), ctr);
                ctr *= inv;
#pragma unroll
                for (int o = 1; o < 8; o <<= 1) ctr += __shfl_xor_sync(~0u, ctr, o);
                // after the 8-lane butterfly every lane of the group holds the
                // row total exactly once; accumulate it once per lane.
                kl_acc += ctr;
            }
        }
        // cross-group reduce: each lane holds its OWN group's total (replicated
        // within the group). xor 8/16 adds the other three groups exactly once.
        kl_acc += __shfl_xor_sync(~0u, kl_acc, 8);
        kl_acc += __shfl_xor_sync(~0u, kl_acc, 16);
        if (lane == 0) red[wid] = kl_acc;
    }

    // ---- join + deterministic grid reduction (fixed-point atomics) ----
    __syncthreads();
    if (tid == 0) {
        float sp = 0.f, sk = 0.f;
#pragma unroll
        for (int w = 0; w < 8; w++) { sp += red[w]; sk += red[8 + w]; }
        const double part = -0.5 * (double)sp - (double)sk;
        const long long q = llrint(part * FIXSCALE);
        atomicAdd(&g_acc, (ull)q);
        __threadfence();
        const unsigned t = atomicAdd(&g_cnt, 1u);
        if (t == NBLK - 1) {
            const long long tot = (long long)atomicAdd(&g_acc, 0ull);
            out[0] = (float)((double)tot / FIXSCALE / 16384.0
                             - 0.5 * LOG2PI * (double)XD);
            g_cnt = 0u;
            g_acc = 0ull;
        }
    }
}

extern "C" void kernel_launch(void* const* d_in, const int* in_sizes, int n_in,
                              void* d_out, int out_size) {
    (void)in_sizes; (void)n_in; (void)out_size;
    const float* x    = (const float*)d_in[0];
    const float* pi   = (const float*)d_in[1];
    const float* qmu  = (const float*)d_in[2];
    const float* qls  = (const float*)d_in[3];
    const float* eps  = (const float*)d_in[4];
    const float* pmu  = (const float*)d_in[5];
    const float* pls  = (const float*)d_in[6];
    const float* W    = (const float*)d_in[7];
    const float* bdec = (const float*)d_in[8];

    cudaFuncSetAttribute(main_kernel, cudaFuncAttributeMaxDynamicSharedMemorySize,
                         SMEM_BYTES);
    prep_kernel<<<15, 256>>>(W, pmu, pls);
    main_kernel<<<NBLK, THREADS, SMEM_BYTES>>>(x, pi, qmu, qls, eps, bdec,
                                               (float*)d_out);
}